// round 15
// baseline (speedup 1.0000x reference)
#include <cuda_runtime.h>
#include <cstdint>
#include <math.h>

#define L_TOT   12544
#define C_IN    64
#define C_OUT   64
#define K_TOT   576
#define KC      32
#define NCHUNK  18            // 9 taps x 2 channel-halves
#define NTHREADS 512

#define PAD_W   114
#define PAD_S   (PAD_W * PAD_W)    // 12996
#define PS2     13056              // plane stride with slack (max pix ~13011)
#define NBATCH  8

// ---- smem layout: header + double-buffered A (2x48KB) + double-buffered B (2x8KB) ----
#define OFF_TMEM  0
#define OFF_MBAR0 8
#define OFF_MBAR1 16
#define OFF_A     1024
#define A_SSTRIDE 49152            // one stage: A1,A2,A3 (3 x 16KB)
#define A_PSTRIDE 16384
#define OFF_B     (OFF_A + 2 * A_SSTRIDE)   // 99328
#define B_SSTRIDE 8192
#define SMEM_TOTAL (OFF_B + 2 * B_SSTRIDE)  // 115712 -> 2 CTAs/SM

// idesc: dtype=F32(1<<4), atype=TF32(2<<7), btype=TF32(2<<10), N=64(8<<17), M=128(8<<24)
#define IDESC_TF32 0x8100910u

#if defined(__CUDA_ARCH_FEAT_SM103_ALL) || \
    (defined(__CUDA_ARCH_SPECIFIC__) && (__CUDA_ARCH_SPECIFIC__ == 1030)) || \
    (defined(__CUDA_ARCH_FAMILY_SPECIFIC__) && (__CUDA_ARCH_FAMILY_SPECIFIC__ == 1030))
#define HAS_TCGEN05 1
#else
#define HAS_TCGEN05 0
#endif

// scratch: transposed pre-powered tf32-rounded planes [b][pix][c], reordered weights
__device__ __align__(16) float g_u1[NBATCH * PS2 * C_IN];   // 26.7MB each
__device__ __align__(16) float g_u2[NBATCH * PS2 * C_IN];
__device__ __align__(16) float g_u3[NBATCH * PS2 * C_IN];
__device__ __align__(16) float g_wtfR[NCHUNK * C_OUT * KC]; // [ch][o][kk], tf32-rounded
__device__ float g_wsum[C_OUT];

__device__ __forceinline__ float tf32r_(float x) {
    float y; asm("cvt.rna.tf32.f32 %0, %1;" : "=f"(y) : "f"(x)); return y;
}

// rowsum + tap-major reordered tf32 weight copy: one warp per output channel
// k' = ch*32 + kk  <->  tap t = ch>>1, channel c = (ch&1)*32 + kk, orig k = c*9 + t
__global__ void wprep_kernel(const float* __restrict__ w) {
    int o    = blockIdx.x * (blockDim.x >> 5) + (threadIdx.x >> 5);
    int lane = threadIdx.x & 31;
    if (o >= C_OUT) return;
    float s = 0.f;
    #pragma unroll
    for (int kp = lane; kp < K_TOT; kp += 32) {
        int ch = kp >> 5, kk = kp & 31;
        int c = ((ch & 1) << 5) + kk;
        int t = ch >> 1;
        float v = w[o * K_TOT + c * 9 + t];
        s += v;
        g_wtfR[(ch * C_OUT + o) * KC + kk] = tf32r_(v);
    }
    #pragma unroll
    for (int d = 16; d > 0; d >>= 1)
        s += __shfl_xor_sync(0xFFFFFFFFu, s, d);
    if (lane == 0) g_wsum[o] = s;
}

// transpose + pad + power + round: img[b][c][y][x] -> g_u{1,2,3}[b][pix][c]
// grid (ceil(PAD_S/32), B), block (32, 8). smem tiles [32 pix][65] per poly.
__global__ void uprep_kernel(const float* __restrict__ img) {
    __shared__ float s1[32 * 65], s2[32 * 65], s3[32 * 65];
    const int b = blockIdx.y;
    const int pix0 = blockIdx.x * 32;
    const int tx = threadIdx.x, ty = threadIdx.y;   // tx: pix offset, ty: c-group
    const int pix = pix0 + tx;
    int py = pix / PAD_W, px = pix - py * PAD_W;
    bool inb = (pix < PAD_S) && ((unsigned)(py - 1) < 112u) && ((unsigned)(px - 1) < 112u);
    int ii = (py - 1) * 112 + (px - 1);
    #pragma unroll
    for (int cc = 0; cc < 8; ++cc) {
        int c = cc * 8 + ty;
        float v = inb ? tf32r_(img[((size_t)(b * C_IN + c)) * L_TOT + ii]) : 0.f;
        float v2 = v * v;
        s1[tx * 65 + c] = v;
        s2[tx * 65 + c] = tf32r_(v2);
        s3[tx * 65 + c] = tf32r_(v2 * v);
    }
    __syncthreads();
    const int tid = ty * 32 + tx;   // 0..255
    #pragma unroll
    for (int j = 0; j < 8; ++j) {
        int idx = j * 256 + tid;
        int pl = idx >> 6, c = idx & 63;
        int p = pix0 + pl;
        if (p < PAD_S) {
            size_t go = ((size_t)b * PS2 + p) * 64 + c;
            g_u1[go] = s1[pl * 65 + c];
            g_u2[go] = s2[pl * 65 + c];
            g_u3[go] = s3[pl * 65 + c];
        }
    }
}

__device__ __forceinline__ float sigm(float x) { return 1.f / (1.f + __expf(-x)); }

__device__ __forceinline__ float epilogue(float S, float c1, float c2, float c3) {
    const float Kf = (float)K_TOT;
    float f = (-0.000287f * S + 0.266f * c1 - 0.1097f * c2) * (1.f / 75.f);

    float g1 = (0.11f  / 75.f) * Kf + 0.001309f * S + 0.00619f  * c1 - 0.009f    * c2 + 0.001383f * c3;
    float g2 = (0.179f / 75.f) * Kf - 0.0025f   * S + 0.00303f  * c1 - 0.00484f  * c2 + 0.0175f   * c3;
    float g3 = (0.238f / 75.f) * Kf - 0.000954f * S + 0.00187f  * c1 + 0.001877f * c2 + 0.01502f  * c3;
    float g4 = (0.388f / 75.f) * Kf - 0.00734f  * S + 0.001117f * c1 + 0.00752f  * c2 + 0.009f    * c3;
    float g5 = (0.507f / 75.f) * Kf - 0.01017f  * S + 0.000426f * c1 + 0.00837f  * c2 + 0.00413f  * c3;

    float t1 = sigm(10.f * (0.15f - f));
    float t2 = sigm(10.f * (0.23f - f));
    float t3 = sigm(10.f * (0.32f - f));
    float t4 = sigm(10.f * (0.39f - f));

    return g5 + t1 * (g1 - g2) + t2 * (g2 - g3) + t3 * (g3 - g4) + t4 * (g4 - g5);
}

#if HAS_TCGEN05
// ---------------- PTX helpers (sm_103a only) ----------------
__device__ __forceinline__ uint32_t smem_u32(const void* p) {
    uint32_t a;
    asm("{ .reg .u64 t; cvta.to.shared.u64 t, %1; cvt.u32.u64 %0, t; }" : "=r"(a) : "l"(p));
    return a;
}
__device__ __forceinline__ uint32_t elect_one() {
    uint32_t p;
    asm volatile("{ .reg .pred p; elect.sync _|p, 0xFFFFFFFF; selp.b32 %0, 1, 0, p; }" : "=r"(p));
    return p;
}

#define MBARRIER_INIT(addr, cnt) \
    asm volatile("mbarrier.init.shared.b64 [%0], %1;" :: "r"((uint32_t)(addr)), "r"((uint32_t)(cnt)) : "memory")

#define MBARRIER_WAIT_PARITY(mb, par) do {                                          \
    uint32_t _mb = (uint32_t)(mb), _p = (uint32_t)(par), _d;                        \
    asm volatile("{ .reg .pred p; mbarrier.try_wait.parity.acquire.cta.shared::cta.b64 p, [%1], %2; selp.b32 %0,1,0,p; }" \
        : "=r"(_d) : "r"(_mb), "r"(_p) : "memory");                                 \
    if (!_d) {                                                                      \
        asm volatile("{ .reg .pred P1;\n\t"                                         \
            "WL_%=: mbarrier.try_wait.parity.acquire.cta.shared::cta.b64 P1, [%0], %1, 0x989680;\n\t" \
            "@P1 bra.uni WD_%=;\n\t bra.uni WL_%=;\n\t WD_%=: }"                    \
            :: "r"(_mb), "r"(_p) : "memory");                                       \
    }                                                                               \
} while (0)

#define TCGEN05_ALLOC(sm, n) \
    asm volatile("tcgen05.alloc.cta_group::1.sync.aligned.shared::cta.b32 [%0], %1;" \
        :: "r"((uint32_t)(sm)), "r"((uint32_t)(n)) : "memory")
#define TCGEN05_RELINQ() \
    asm volatile("tcgen05.relinquish_alloc_permit.cta_group::1.sync.aligned;")
#define TCGEN05_DEALLOC(t, n) \
    asm volatile("tcgen05.dealloc.cta_group::1.sync.aligned.b32 %0, %1;" :: "r"(t), "r"((uint32_t)(n)))
#define TCGEN05_COMMIT(mb) \
    asm volatile("tcgen05.commit.cta_group::1.mbarrier::arrive::one.shared::cluster.b64 [%0];" \
        :: "r"((uint32_t)(mb)) : "memory")
#define TCGEN05_WAIT_LD()  asm volatile("tcgen05.wait::ld.sync.aligned;" ::: "memory")
#define TCGEN05_FENCE_AFTER() asm volatile("tcgen05.fence::after_thread_sync;" ::: "memory")

#define TCGEN05_LD_X16(r, addr) \
    asm volatile("tcgen05.ld.sync.aligned.32x32b.x16.b32 " \
        "{%0,%1,%2,%3,%4,%5,%6,%7,%8,%9,%10,%11,%12,%13,%14,%15}, [%16];" \
        : "=r"((r)[0]),"=r"((r)[1]),"=r"((r)[2]),"=r"((r)[3]),   \
          "=r"((r)[4]),"=r"((r)[5]),"=r"((r)[6]),"=r"((r)[7]),   \
          "=r"((r)[8]),"=r"((r)[9]),"=r"((r)[10]),"=r"((r)[11]), \
          "=r"((r)[12]),"=r"((r)[13]),"=r"((r)[14]),"=r"((r)[15]) \
        : "r"(addr))

// SW128 K-major smem descriptor (layout=2, version=1, SBO=64, LBO=1)
__device__ __forceinline__ uint64_t make_desc_sw128(uint32_t addr) {
    return ((uint64_t)2 << 61) | ((uint64_t)1 << 46) | ((uint64_t)64 << 32) |
           ((uint64_t)1 << 16) | ((uint64_t)(addr >> 4) & 0x3FFF);
}

__device__ __forceinline__ void mma_tf32_ss(uint32_t d, uint64_t ad, uint64_t bd,
                                            uint32_t idesc, uint32_t en) {
    asm volatile(
        "{ .reg .pred p; setp.ne.u32 p, %4, 0;\n\t"
        "tcgen05.mma.cta_group::1.kind::tf32 [%0], %1, %2, %3, {%5,%5,%5,%5}, p; }\n"
        :: "r"(d), "l"(ad), "l"(bd), "r"(idesc), "r"(en), "r"(0u) : "memory");
}
#endif // HAS_TCGEN05

// ---------------- main kernel: tile = (batch, image row), M=128 (112 real) ----------------
__global__ __launch_bounds__(NTHREADS, 2) void conv_tc_kernel(
    const float* __restrict__ img,
    const float* __restrict__ wts,
    float* __restrict__ out)
{
#if HAS_TCGEN05
    extern __shared__ char smem[];
    const uint32_t sb = smem_u32(smem);
    const int tid = threadIdx.x, wid = tid >> 5, lane = tid & 31;
    const int bx = blockIdx.x;
    const int b = bx / 112, y = bx - b * 112;

    // TMEM alloc + mbar init
    if (wid == 0) { TCGEN05_ALLOC(sb + OFF_TMEM, 256); TCGEN05_RELINQ(); }
    if (tid == 0) { MBARRIER_INIT(sb + OFF_MBAR0, 1); MBARRIER_INIT(sb + OFF_MBAR1, 1); }
    __syncthreads();
    uint32_t tmem;
    asm volatile("ld.shared.b32 %0, [%1];" : "=r"(tmem) : "r"(sb + OFF_TMEM));

    // staging assignment: kq = tid&7 (k-quad), m0 = tid>>3 (row; also row m0+64). B uses same map (o=m0).
    const int kq = tid & 7, m0 = tid >> 3;
    uint32_t swA0, swA1;
    { uint32_t v = (uint32_t)(m0 * 128 + kq * 16);        swA0 = v ^ ((v >> 3) & 0x70); }
    { uint32_t v = (uint32_t)((m0 + 64) * 128 + kq * 16); swA1 = v ^ ((v >> 3) & 0x70); }

    const size_t planebase = (size_t)b * PS2 * 64;
    const float* u1p = g_u1 + planebase;
    const float* u2p = g_u2 + planebase;
    const float* u3p = g_u3 + planebase;

    // register prefetch buffers: 6 A float4 + 1 B float4
    float4 a1l, a1h, a2l, a2h, a3l, a3h, bw;

    #define PREFETCH(CH) do {                                                   \
        int _t = (CH) >> 1;                                                     \
        int _dy = (_t >= 6) ? 2 : (_t >= 3 ? 1 : 0);                            \
        int _dx = _t - _dy * 3;                                                 \
        int _c0 = ((CH) & 1) << 5;                                              \
        size_t _base = (size_t)((y + _dy) * PAD_W + _dx) * 64 + _c0 + kq * 4;   \
        size_t _bl = _base + m0 * 64, _bh = _base + (m0 + 64) * 64;             \
        a1l = *(const float4*)(u1p + _bl);  a1h = *(const float4*)(u1p + _bh);  \
        a2l = *(const float4*)(u2p + _bl);  a2h = *(const float4*)(u2p + _bh);  \
        a3l = *(const float4*)(u3p + _bl);  a3h = *(const float4*)(u3p + _bh);  \
        bw  = *(const float4*)(g_wtfR + ((CH) * C_OUT + m0) * KC + kq * 4);     \
    } while (0)

    PREFETCH(0);

    int ph0 = 0, ph1 = 0;
    for (int ch = 0; ch < NCHUNK; ++ch) {
        const int s = ch & 1;
        const uint32_t mbar = sb + (s ? OFF_MBAR1 : OFF_MBAR0);
        if (ch >= 2) {
            if (s) { MBARRIER_WAIT_PARITY(mbar, ph1); ph1 ^= 1; }
            else   { MBARRIER_WAIT_PARITY(mbar, ph0); ph0 ^= 1; }
        }
        char* Abase = smem + OFF_A + s * A_SSTRIDE;
        char* Bbase = smem + OFF_B + s * B_SSTRIDE;

        // ---- pure STS staging (everything pre-rounded) ----
        *(float4*)(Abase + 0 * A_PSTRIDE + swA0) = a1l;
        *(float4*)(Abase + 0 * A_PSTRIDE + swA1) = a1h;
        *(float4*)(Abase + 1 * A_PSTRIDE + swA0) = a2l;
        *(float4*)(Abase + 1 * A_PSTRIDE + swA1) = a2h;
        *(float4*)(Abase + 2 * A_PSTRIDE + swA0) = a3l;
        *(float4*)(Abase + 2 * A_PSTRIDE + swA1) = a3h;
        *(float4*)(Bbase + swA0) = bw;
        asm volatile("fence.proxy.async.shared::cta;" ::: "memory");
        __syncthreads();

        // ---- issue MMAs for this chunk ----
        if (wid == 0 && elect_one()) {
            const uint32_t ab = sb + OFF_A + s * A_SSTRIDE;
            const uint64_t ad1 = make_desc_sw128(ab);
            const uint64_t ad2 = make_desc_sw128(ab + A_PSTRIDE);
            const uint64_t ad3 = make_desc_sw128(ab + 2 * A_PSTRIDE);
            const uint64_t bd  = make_desc_sw128(sb + OFF_B + s * B_SSTRIDE);
            #pragma unroll
            for (int st = 0; st < 4; ++st) {
                uint32_t en = (ch > 0 || st > 0) ? 1u : 0u;
                mma_tf32_ss(tmem + 0,   ad1 + st * 2, bd + st * 2, IDESC_TF32, en);
                mma_tf32_ss(tmem + 64,  ad2 + st * 2, bd + st * 2, IDESC_TF32, en);
                mma_tf32_ss(tmem + 128, ad3 + st * 2, bd + st * 2, IDESC_TF32, en);
            }
            TCGEN05_COMMIT(mbar);
        }

        // ---- prefetch next chunk (overlaps MMAs) ----
        if (ch + 1 < NCHUNK) PREFETCH(ch + 1);
    }
    MBARRIER_WAIT_PARITY(sb + OFF_MBAR0, ph0);
    MBARRIER_WAIT_PARITY(sb + OFF_MBAR1, ph1);

    // ---- fused epilogue from TMEM (16 warps: warp -> (m-subpartition, 16-col group)) ----
    TCGEN05_FENCE_AFTER();
    const int msub = wid & 3;
    const int n0   = (wid >> 2) * 16;
    const int mloc = msub * 32 + lane;          // 0..127; valid if < 112

    {
        uint32_t a1[16], a2[16], a3[16];
        TCGEN05_LD_X16(a1, tmem + 0   + n0);
        TCGEN05_LD_X16(a2, tmem + 64  + n0);
        TCGEN05_LD_X16(a3, tmem + 128 + n0);
        TCGEN05_WAIT_LD();
        if (mloc < 112) {
            #pragma unroll
            for (int ni = 0; ni < 16; ++ni) {
                const int o = n0 + ni;
                float res = epilogue(__ldg(g_wsum + o),
                                     __uint_as_float(a1[ni]),
                                     __uint_as_float(a2[ni]),
                                     __uint_as_float(a3[ni]));
                out[(size_t)(b * C_OUT + o) * L_TOT + y * 112 + mloc] = res;
            }
        }
    }

    __syncthreads();
    if (wid == 0) TCGEN05_DEALLOC(tmem, 256);
#else
    // ---------- fallback for non-sm_103a compilation passes (never runs on GB300) ----------
    const int tid = threadIdx.x;
    const int bx = blockIdx.x;
    const int b = bx / 112, y = bx - b * 112;
    const float* imgb = img + (size_t)b * C_IN * L_TOT;

    for (int idx = tid; idx < 112 * C_OUT; idx += NTHREADS) {
        int x = idx % 112, o = idx / 112;
        float c1 = 0.f, c2 = 0.f, c3 = 0.f;
        for (int k = 0; k < K_TOT; ++k) {
            int c = k / 9, r = k - c * 9, dy = r / 3, dx = r - dy * 3;
            int iy = y + dy - 1, ix = x + dx - 1;
            float v = 0.f;
            if ((unsigned)iy < 112u && (unsigned)ix < 112u)
                v = imgb[c * L_TOT + iy * 112 + ix];
            float w = wts[o * K_TOT + k];
            c1 += v * w; c2 += v * v * w; c3 += v * v * v * w;
        }
        out[(size_t)(b * C_OUT + o) * L_TOT + y * 112 + x] = epilogue(g_wsum[o], c1, c2, c3);
    }
#endif
}

extern "C" void kernel_launch(void* const* d_in, const int* in_sizes, int n_in,
                              void* d_out, int out_size) {
    const float* img = (const float*)d_in[0];
    const float* wts = (const float*)d_in[1];
    float* out = (float*)d_out;

    int B = in_sizes[0] / (C_IN * L_TOT);   // 8

    cudaFuncSetAttribute(conv_tc_kernel, cudaFuncAttributeMaxDynamicSharedMemorySize, SMEM_TOTAL);

    wprep_kernel<<<4, 512>>>(wts);
    {
        dim3 pg((PAD_S + 31) / 32, B);
        uprep_kernel<<<pg, dim3(32, 8)>>>(img);
    }
    conv_tc_kernel<<<B * 112, NTHREADS, SMEM_TOTAL>>>(img, wts, out);
}

// round 16
// speedup vs baseline: 1.2729x; 1.2729x over previous
#include <cuda_runtime.h>
#include <cstdint>
#include <math.h>

#define L_TOT   12544
#define C_IN    64
#define C_OUT   64
#define K_TOT   576
#define KC      32
#define NCHUNK  18            // 9 taps x 2 channel-halves
#define NTHREADS 512

#define PAD_W   114
#define PAD_S   (PAD_W * PAD_W)    // 12996
#define PS2     13056              // plane stride with slack
#define NBATCH  8

// ---- smem layout: header + double-buffered A (2x48KB) + double-buffered B (2x8KB) ----
#define OFF_TMEM  0
#define OFF_MBAR0 8
#define OFF_MBAR1 16
#define OFF_A     1024
#define A_SSTRIDE 49152            // one stage: A1,A2,A3 (3 x 16KB)
#define A_PSTRIDE 16384
#define OFF_B     (OFF_A + 2 * A_SSTRIDE)   // 99328
#define B_SSTRIDE 8192
#define SMEM_TOTAL (OFF_B + 2 * B_SSTRIDE)  // 115712 -> 2 CTAs/SM

// idesc: dtype=F32(1<<4), atype=TF32(2<<7), btype=TF32(2<<10), N=64(8<<17), M=128(8<<24)
#define IDESC_TF32 0x8100910u

#if defined(__CUDA_ARCH_FEAT_SM103_ALL) || \
    (defined(__CUDA_ARCH_SPECIFIC__) && (__CUDA_ARCH_SPECIFIC__ == 1030)) || \
    (defined(__CUDA_ARCH_FAMILY_SPECIFIC__) && (__CUDA_ARCH_FAMILY_SPECIFIC__ == 1030))
#define HAS_TCGEN05 1
#else
#define HAS_TCGEN05 0
#endif

// scratch: transposed tf32-rounded u plane [b][pix][c] (L2-resident, 26.7MB)
__device__ __align__(16) float g_u1[NBATCH * PS2 * C_IN];
__device__ __align__(16) float g_wtfR[NCHUNK * C_OUT * KC]; // [ch][o][kk], tap-major, tf32
__device__ float g_wsum[C_OUT];

__device__ __forceinline__ float tf32r_(float x) {
    float y; asm("cvt.rna.tf32.f32 %0, %1;" : "=f"(y) : "f"(x)); return y;
}

// rowsum + tap-major reordered tf32 weight copy: one warp per output channel
// k' = ch*32 + kk  <->  tap t = ch>>1, channel c = (ch&1)*32 + kk, orig k = c*9 + t
__global__ void wprep_kernel(const float* __restrict__ w) {
    int o    = blockIdx.x * (blockDim.x >> 5) + (threadIdx.x >> 5);
    int lane = threadIdx.x & 31;
    if (o >= C_OUT) return;
    float s = 0.f;
    #pragma unroll
    for (int kp = lane; kp < K_TOT; kp += 32) {
        int ch = kp >> 5, kk = kp & 31;
        int c = ((ch & 1) << 5) + kk;
        int t = ch >> 1;
        float v = w[o * K_TOT + c * 9 + t];
        s += v;
        g_wtfR[(ch * C_OUT + o) * KC + kk] = tf32r_(v);
    }
    #pragma unroll
    for (int d = 16; d > 0; d >>= 1)
        s += __shfl_xor_sync(0xFFFFFFFFu, s, d);
    if (lane == 0) g_wsum[o] = s;
}

// transpose + pad + round: img[b][c][y][x] -> g_u1[b][pix][c]
// grid (ceil(PAD_S/32), B), block (32, 8). smem tile [32 pix][65].
__global__ void uprep_kernel(const float* __restrict__ img) {
    __shared__ float s1[32 * 65];
    const int b = blockIdx.y;
    const int pix0 = blockIdx.x * 32;
    const int tx = threadIdx.x, ty = threadIdx.y;
    const int pix = pix0 + tx;
    int py = pix / PAD_W, px = pix - py * PAD_W;
    bool inb = (pix < PAD_S) && ((unsigned)(py - 1) < 112u) && ((unsigned)(px - 1) < 112u);
    int ii = (py - 1) * 112 + (px - 1);
    #pragma unroll
    for (int cc = 0; cc < 8; ++cc) {
        int c = cc * 8 + ty;
        float v = inb ? tf32r_(img[((size_t)(b * C_IN + c)) * L_TOT + ii]) : 0.f;
        s1[tx * 65 + c] = v;
    }
    __syncthreads();
    const int tid = ty * 32 + tx;   // 0..255
    #pragma unroll
    for (int j = 0; j < 8; ++j) {
        int idx = j * 256 + tid;
        int pl = idx >> 6, c = idx & 63;
        int p = pix0 + pl;
        if (p < PAD_S)
            g_u1[((size_t)b * PS2 + p) * 64 + c] = s1[pl * 65 + c];
    }
}

__device__ __forceinline__ float sigm(float x) { return 1.f / (1.f + __expf(-x)); }

__device__ __forceinline__ float epilogue(float S, float c1, float c2, float c3) {
    const float Kf = (float)K_TOT;
    float f = (-0.000287f * S + 0.266f * c1 - 0.1097f * c2) * (1.f / 75.f);

    float g1 = (0.11f  / 75.f) * Kf + 0.001309f * S + 0.00619f  * c1 - 0.009f    * c2 + 0.001383f * c3;
    float g2 = (0.179f / 75.f) * Kf - 0.0025f   * S + 0.00303f  * c1 - 0.00484f  * c2 + 0.0175f   * c3;
    float g3 = (0.238f / 75.f) * Kf - 0.000954f * S + 0.00187f  * c1 + 0.001877f * c2 + 0.01502f  * c3;
    float g4 = (0.388f / 75.f) * Kf - 0.00734f  * S + 0.001117f * c1 + 0.00752f  * c2 + 0.009f    * c3;
    float g5 = (0.507f / 75.f) * Kf - 0.01017f  * S + 0.000426f * c1 + 0.00837f  * c2 + 0.00413f  * c3;

    float t1 = sigm(10.f * (0.15f - f));
    float t2 = sigm(10.f * (0.23f - f));
    float t3 = sigm(10.f * (0.32f - f));
    float t4 = sigm(10.f * (0.39f - f));

    return g5 + t1 * (g1 - g2) + t2 * (g2 - g3) + t3 * (g3 - g4) + t4 * (g4 - g5);
}

#if HAS_TCGEN05
// ---------------- PTX helpers (sm_103a only) ----------------
__device__ __forceinline__ uint32_t smem_u32(const void* p) {
    uint32_t a;
    asm("{ .reg .u64 t; cvta.to.shared.u64 t, %1; cvt.u32.u64 %0, t; }" : "=r"(a) : "l"(p));
    return a;
}
__device__ __forceinline__ uint32_t elect_one() {
    uint32_t p;
    asm volatile("{ .reg .pred p; elect.sync _|p, 0xFFFFFFFF; selp.b32 %0, 1, 0, p; }" : "=r"(p));
    return p;
}

#define MBARRIER_INIT(addr, cnt) \
    asm volatile("mbarrier.init.shared.b64 [%0], %1;" :: "r"((uint32_t)(addr)), "r"((uint32_t)(cnt)) : "memory")

#define MBARRIER_WAIT_PARITY(mb, par) do {                                          \
    uint32_t _mb = (uint32_t)(mb), _p = (uint32_t)(par), _d;                        \
    asm volatile("{ .reg .pred p; mbarrier.try_wait.parity.acquire.cta.shared::cta.b64 p, [%1], %2; selp.b32 %0,1,0,p; }" \
        : "=r"(_d) : "r"(_mb), "r"(_p) : "memory");                                 \
    if (!_d) {                                                                      \
        asm volatile("{ .reg .pred P1;\n\t"                                         \
            "WL_%=: mbarrier.try_wait.parity.acquire.cta.shared::cta.b64 P1, [%0], %1, 0x989680;\n\t" \
            "@P1 bra.uni WD_%=;\n\t bra.uni WL_%=;\n\t WD_%=: }"                    \
            :: "r"(_mb), "r"(_p) : "memory");                                       \
    }                                                                               \
} while (0)

#define TCGEN05_ALLOC(sm, n) \
    asm volatile("tcgen05.alloc.cta_group::1.sync.aligned.shared::cta.b32 [%0], %1;" \
        :: "r"((uint32_t)(sm)), "r"((uint32_t)(n)) : "memory")
#define TCGEN05_RELINQ() \
    asm volatile("tcgen05.relinquish_alloc_permit.cta_group::1.sync.aligned;")
#define TCGEN05_DEALLOC(t, n) \
    asm volatile("tcgen05.dealloc.cta_group::1.sync.aligned.b32 %0, %1;" :: "r"(t), "r"((uint32_t)(n)))
#define TCGEN05_COMMIT(mb) \
    asm volatile("tcgen05.commit.cta_group::1.mbarrier::arrive::one.shared::cluster.b64 [%0];" \
        :: "r"((uint32_t)(mb)) : "memory")
#define TCGEN05_WAIT_LD()  asm volatile("tcgen05.wait::ld.sync.aligned;" ::: "memory")
#define TCGEN05_FENCE_AFTER() asm volatile("tcgen05.fence::after_thread_sync;" ::: "memory")

#define TCGEN05_LD_X16(r, addr) \
    asm volatile("tcgen05.ld.sync.aligned.32x32b.x16.b32 " \
        "{%0,%1,%2,%3,%4,%5,%6,%7,%8,%9,%10,%11,%12,%13,%14,%15}, [%16];" \
        : "=r"((r)[0]),"=r"((r)[1]),"=r"((r)[2]),"=r"((r)[3]),   \
          "=r"((r)[4]),"=r"((r)[5]),"=r"((r)[6]),"=r"((r)[7]),   \
          "=r"((r)[8]),"=r"((r)[9]),"=r"((r)[10]),"=r"((r)[11]), \
          "=r"((r)[12]),"=r"((r)[13]),"=r"((r)[14]),"=r"((r)[15]) \
        : "r"(addr))

// SW128 K-major smem descriptor (layout=2, version=1, SBO=64, LBO=1)
__device__ __forceinline__ uint64_t make_desc_sw128(uint32_t addr) {
    return ((uint64_t)2 << 61) | ((uint64_t)1 << 46) | ((uint64_t)64 << 32) |
           ((uint64_t)1 << 16) | ((uint64_t)(addr >> 4) & 0x3FFF);
}

__device__ __forceinline__ void mma_tf32_ss(uint32_t d, uint64_t ad, uint64_t bd,
                                            uint32_t idesc, uint32_t en) {
    asm volatile(
        "{ .reg .pred p; setp.ne.u32 p, %4, 0;\n\t"
        "tcgen05.mma.cta_group::1.kind::tf32 [%0], %1, %2, %3, {%5,%5,%5,%5}, p; }\n"
        :: "r"(d), "l"(ad), "l"(bd), "r"(idesc), "r"(en), "r"(0u) : "memory");
}
#endif // HAS_TCGEN05

// ---------------- main kernel: tile = (batch, image row), M=128 (112 real) ----------------
__global__ __launch_bounds__(NTHREADS, 2) void conv_tc_kernel(
    const float* __restrict__ img,
    const float* __restrict__ wts,
    float* __restrict__ out)
{
#if HAS_TCGEN05
    extern __shared__ char smem[];
    const uint32_t sb = smem_u32(smem);
    const int tid = threadIdx.x, wid = tid >> 5, lane = tid & 31;
    const int bx = blockIdx.x;
    const int b = bx / 112, y = bx - b * 112;

    // TMEM alloc + mbar init
    if (wid == 0) { TCGEN05_ALLOC(sb + OFF_TMEM, 256); TCGEN05_RELINQ(); }
    if (tid == 0) { MBARRIER_INIT(sb + OFF_MBAR0, 1); MBARRIER_INIT(sb + OFF_MBAR1, 1); }
    __syncthreads();
    uint32_t tmem;
    asm volatile("ld.shared.b32 %0, [%1];" : "=r"(tmem) : "r"(sb + OFF_TMEM));

    // staging: kq = tid&7 (16B quad within 32-ch row), m0 = tid>>3 (rows m0, m0+64)
    const int kq = tid & 7, m0 = tid >> 3;
    uint32_t swA0, swA1;
    { uint32_t v = (uint32_t)(m0 * 128 + kq * 16);        swA0 = v ^ ((v >> 3) & 0x70); }
    { uint32_t v = (uint32_t)((m0 + 64) * 128 + kq * 16); swA1 = v ^ ((v >> 3) & 0x70); }

    const float* u1p = g_u1 + (size_t)b * PS2 * 64;

    // register prefetch buffers: 2 u float4 + 1 B float4
    float4 a1l, a1h, bw;

    #define PREFETCH(CH) do {                                                   \
        int _t = (CH) >> 1;                                                     \
        int _dy = (_t >= 6) ? 2 : (_t >= 3 ? 1 : 0);                            \
        int _dx = _t - _dy * 3;                                                 \
        int _c0 = ((CH) & 1) << 5;                                              \
        size_t _base = (size_t)((y + _dy) * PAD_W + _dx) * 64 + _c0 + kq * 4;   \
        a1l = *(const float4*)(u1p + _base + m0 * 64);                          \
        a1h = *(const float4*)(u1p + _base + (m0 + 64) * 64);                   \
        bw  = *(const float4*)(g_wtfR + ((CH) * C_OUT + m0) * KC + kq * 4);     \
    } while (0)

    PREFETCH(0);

    int ph0 = 0, ph1 = 0;
    for (int ch = 0; ch < NCHUNK; ++ch) {
        const int s = ch & 1;
        const uint32_t mbar = sb + (s ? OFF_MBAR1 : OFF_MBAR0);
        if (ch >= 2) {
            if (s) { MBARRIER_WAIT_PARITY(mbar, ph1); ph1 ^= 1; }
            else   { MBARRIER_WAIT_PARITY(mbar, ph0); ph0 ^= 1; }
        }
        char* Abase = smem + OFF_A + s * A_SSTRIDE;
        char* Bbase = smem + OFF_B + s * B_SSTRIDE;

        // ---- staging: u direct; u^2,u^3 computed+rounded in regs ----
        float4 a2l, a2h, a3l, a3h;
        {
            const float* pl = &a1l.x; const float* ph = &a1h.x;
            float* q2l = &a2l.x; float* q2h = &a2h.x;
            float* q3l = &a3l.x; float* q3h = &a3h.x;
            #pragma unroll
            for (int j = 0; j < 4; ++j) {
                float vl = pl[j], vh = ph[j];
                float vl2 = vl * vl, vh2 = vh * vh;
                q2l[j] = tf32r_(vl2); q2h[j] = tf32r_(vh2);
                q3l[j] = tf32r_(vl2 * vl); q3h[j] = tf32r_(vh2 * vh);
            }
        }
        *(float4*)(Abase + 0 * A_PSTRIDE + swA0) = a1l;
        *(float4*)(Abase + 0 * A_PSTRIDE + swA1) = a1h;
        *(float4*)(Abase + 1 * A_PSTRIDE + swA0) = a2l;
        *(float4*)(Abase + 1 * A_PSTRIDE + swA1) = a2h;
        *(float4*)(Abase + 2 * A_PSTRIDE + swA0) = a3l;
        *(float4*)(Abase + 2 * A_PSTRIDE + swA1) = a3h;
        *(float4*)(Bbase + swA0) = bw;
        asm volatile("fence.proxy.async.shared::cta;" ::: "memory");
        __syncthreads();

        // ---- issue MMAs for this chunk ----
        if (wid == 0 && elect_one()) {
            const uint32_t ab = sb + OFF_A + s * A_SSTRIDE;
            const uint64_t ad1 = make_desc_sw128(ab);
            const uint64_t ad2 = make_desc_sw128(ab + A_PSTRIDE);
            const uint64_t ad3 = make_desc_sw128(ab + 2 * A_PSTRIDE);
            const uint64_t bd  = make_desc_sw128(sb + OFF_B + s * B_SSTRIDE);
            #pragma unroll
            for (int st = 0; st < 4; ++st) {
                uint32_t en = (ch > 0 || st > 0) ? 1u : 0u;
                mma_tf32_ss(tmem + 0,   ad1 + st * 2, bd + st * 2, IDESC_TF32, en);
                mma_tf32_ss(tmem + 64,  ad2 + st * 2, bd + st * 2, IDESC_TF32, en);
                mma_tf32_ss(tmem + 128, ad3 + st * 2, bd + st * 2, IDESC_TF32, en);
            }
            TCGEN05_COMMIT(mbar);
        }

        // ---- prefetch next chunk (overlaps MMAs) ----
        if (ch + 1 < NCHUNK) PREFETCH(ch + 1);
    }
    MBARRIER_WAIT_PARITY(sb + OFF_MBAR0, ph0);
    MBARRIER_WAIT_PARITY(sb + OFF_MBAR1, ph1);

    // ---- fused epilogue from TMEM (16 warps: warp -> (m-subpartition, 16-col group)) ----
    TCGEN05_FENCE_AFTER();
    const int msub = wid & 3;
    const int n0   = (wid >> 2) * 16;
    const int mloc = msub * 32 + lane;          // 0..127; valid if < 112

    {
        uint32_t a1[16], a2[16], a3[16];
        TCGEN05_LD_X16(a1, tmem + 0   + n0);
        TCGEN05_LD_X16(a2, tmem + 64  + n0);
        TCGEN05_LD_X16(a3, tmem + 128 + n0);
        TCGEN05_WAIT_LD();
        if (mloc < 112) {
            #pragma unroll
            for (int ni = 0; ni < 16; ++ni) {
                const int o = n0 + ni;
                float res = epilogue(__ldg(g_wsum + o),
                                     __uint_as_float(a1[ni]),
                                     __uint_as_float(a2[ni]),
                                     __uint_as_float(a3[ni]));
                out[(size_t)(b * C_OUT + o) * L_TOT + y * 112 + mloc] = res;
            }
        }
    }

    __syncthreads();
    if (wid == 0) TCGEN05_DEALLOC(tmem, 256);
#else
    // ---------- fallback for non-sm_103a compilation passes (never runs on GB300) ----------
    const int tid = threadIdx.x;
    const int bx = blockIdx.x;
    const int b = bx / 112, y = bx - b * 112;
    const float* imgb = img + (size_t)b * C_IN * L_TOT;

    for (int idx = tid; idx < 112 * C_OUT; idx += NTHREADS) {
        int x = idx % 112, o = idx / 112;
        float c1 = 0.f, c2 = 0.f, c3 = 0.f;
        for (int k = 0; k < K_TOT; ++k) {
            int c = k / 9, r = k - c * 9, dy = r / 3, dx = r - dy * 3;
            int iy = y + dy - 1, ix = x + dx - 1;
            float v = 0.f;
            if ((unsigned)iy < 112u && (unsigned)ix < 112u)
                v = imgb[c * L_TOT + iy * 112 + ix];
            float w = wts[o * K_TOT + k];
            c1 += v * w; c2 += v * v * w; c3 += v * v * v * w;
        }
        out[(size_t)(b * C_OUT + o) * L_TOT + y * 112 + x] = epilogue(g_wsum[o], c1, c2, c3);
    }
#endif
}

extern "C" void kernel_launch(void* const* d_in, const int* in_sizes, int n_in,
                              void* d_out, int out_size) {
    const float* img = (const float*)d_in[0];
    const float* wts = (const float*)d_in[1];
    float* out = (float*)d_out;

    int B = in_sizes[0] / (C_IN * L_TOT);   // 8

    cudaFuncSetAttribute(conv_tc_kernel, cudaFuncAttributeMaxDynamicSharedMemorySize, SMEM_TOTAL);

    wprep_kernel<<<4, 512>>>(wts);
    {
        dim3 pg((PAD_S + 31) / 32, B);
        uprep_kernel<<<pg, dim3(32, 8)>>>(img);
    }
    conv_tc_kernel<<<B * 112, NTHREADS, SMEM_TOTAL>>>(img, wts, out);
}

// round 17
// speedup vs baseline: 1.7711x; 1.3914x over previous
#include <cuda_runtime.h>
#include <cstdint>
#include <math.h>

#define L_TOT   12544
#define C_IN    64
#define C_OUT   64
#define K_TOT   576
#define NSTAGE  6             // 3 dy x 2 channel-halves
#define NTHREADS 512

#define PAD_W   114
#define PAD_S   (PAD_W * PAD_W)    // 12996
#define PS2     13056              // plane stride with slack (max pix used = 13011)
#define NBATCH  8

// ---- smem: header + single-buffer A (3 planes x 136 rows x 128B) + B (3 dx x 8KB) ----
#define OFF_TMEM  0
#define OFF_MBAR0 8
#define OFF_A     1024
#define A_PSTRIDE 17408            // 136 rows x 128B, 1024-aligned
#define OFF_B     (OFF_A + 3 * A_PSTRIDE)   // 53248
#define B_DSTRIDE 8192
#define SMEM_TOTAL (OFF_B + 3 * B_DSTRIDE)  // 77824 -> 2 CTAs/SM (155648 <= 228KB)

// idesc: dtype=F32(1<<4), atype=TF32(2<<7), btype=TF32(2<<10), N=64(8<<17), M=128(8<<24)
#define IDESC_TF32 0x8100910u

#if defined(__CUDA_ARCH_FEAT_SM103_ALL) || \
    (defined(__CUDA_ARCH_SPECIFIC__) && (__CUDA_ARCH_SPECIFIC__ == 1030)) || \
    (defined(__CUDA_ARCH_FAMILY_SPECIFIC__) && (__CUDA_ARCH_FAMILY_SPECIFIC__ == 1030))
#define HAS_TCGEN05 1
#else
#define HAS_TCGEN05 0
#endif

// scratch: transposed tf32-rounded u plane [b][pix][c] (L2-resident, 26.7MB)
__device__ __align__(16) float g_u1[NBATCH * PS2 * C_IN];
// weights: [tile(6*3)][o(64)][kk(32)]: tile = s*3+dx, s = dy*2+half
__device__ __align__(16) float g_wtfR[18 * C_OUT * 32];
__device__ float g_wsum[C_OUT];

__device__ __forceinline__ float tf32r_(float x) {
    float y; asm("cvt.rna.tf32.f32 %0, %1;" : "=f"(y) : "f"(x)); return y;
}

// rowsum + tile-ordered tf32 weight copy: one warp per output channel
// kp = tile*32 + kk; tile = s*3+dx; c = (s&1)*32+kk; tap t' = (s>>1)*3+dx; orig k = c*9+t'
__global__ void wprep_kernel(const float* __restrict__ w) {
    int o    = blockIdx.x * (blockDim.x >> 5) + (threadIdx.x >> 5);
    int lane = threadIdx.x & 31;
    if (o >= C_OUT) return;
    float s = 0.f;
    #pragma unroll
    for (int kp = lane; kp < K_TOT; kp += 32) {
        int tile = kp >> 5, kk = kp & 31;
        int sdx = tile;                 // s*3+dx
        int st_ = sdx / 3, dx = sdx - st_ * 3;
        int c  = ((st_ & 1) << 5) + kk;
        int tp = (st_ >> 1) * 3 + dx;
        float v = w[o * K_TOT + c * 9 + tp];
        s += v;
        g_wtfR[(tile * C_OUT + o) * 32 + kk] = tf32r_(v);
    }
    #pragma unroll
    for (int d = 16; d > 0; d >>= 1)
        s += __shfl_xor_sync(0xFFFFFFFFu, s, d);
    if (lane == 0) g_wsum[o] = s;
}

// transpose + pad + round: img[b][c][y][x] -> g_u1[b][pix][c]
__global__ void uprep_kernel(const float* __restrict__ img) {
    __shared__ float s1[32 * 65];
    const int b = blockIdx.y;
    const int pix0 = blockIdx.x * 32;
    const int tx = threadIdx.x, ty = threadIdx.y;
    const int pix = pix0 + tx;
    int py = pix / PAD_W, px = pix - py * PAD_W;
    bool inb = (pix < PAD_S) && ((unsigned)(py - 1) < 112u) && ((unsigned)(px - 1) < 112u);
    int ii = (py - 1) * 112 + (px - 1);
    #pragma unroll
    for (int cc = 0; cc < 8; ++cc) {
        int c = cc * 8 + ty;
        float v = inb ? tf32r_(img[((size_t)(b * C_IN + c)) * L_TOT + ii]) : 0.f;
        s1[tx * 65 + c] = v;
    }
    __syncthreads();
    const int tid = ty * 32 + tx;
    #pragma unroll
    for (int j = 0; j < 8; ++j) {
        int idx = j * 256 + tid;
        int pl = idx >> 6, c = idx & 63;
        int p = pix0 + pl;
        if (p < PAD_S)
            g_u1[((size_t)b * PS2 + p) * 64 + c] = s1[pl * 65 + c];
    }
}

__device__ __forceinline__ float sigm(float x) { return 1.f / (1.f + __expf(-x)); }

__device__ __forceinline__ float epilogue(float S, float c1, float c2, float c3) {
    const float Kf = (float)K_TOT;
    float f = (-0.000287f * S + 0.266f * c1 - 0.1097f * c2) * (1.f / 75.f);

    float g1 = (0.11f  / 75.f) * Kf + 0.001309f * S + 0.00619f  * c1 - 0.009f    * c2 + 0.001383f * c3;
    float g2 = (0.179f / 75.f) * Kf - 0.0025f   * S + 0.00303f  * c1 - 0.00484f  * c2 + 0.0175f   * c3;
    float g3 = (0.238f / 75.f) * Kf - 0.000954f * S + 0.00187f  * c1 + 0.001877f * c2 + 0.01502f  * c3;
    float g4 = (0.388f / 75.f) * Kf - 0.00734f  * S + 0.001117f * c1 + 0.00752f  * c2 + 0.009f    * c3;
    float g5 = (0.507f / 75.f) * Kf - 0.01017f  * S + 0.000426f * c1 + 0.00837f  * c2 + 0.00413f  * c3;

    float t1 = sigm(10.f * (0.15f - f));
    float t2 = sigm(10.f * (0.23f - f));
    float t3 = sigm(10.f * (0.32f - f));
    float t4 = sigm(10.f * (0.39f - f));

    return g5 + t1 * (g1 - g2) + t2 * (g2 - g3) + t3 * (g3 - g4) + t4 * (g4 - g5);
}

#if HAS_TCGEN05
// ---------------- PTX helpers (sm_103a only) ----------------
__device__ __forceinline__ uint32_t smem_u32(const void* p) {
    uint32_t a;
    asm("{ .reg .u64 t; cvta.to.shared.u64 t, %1; cvt.u32.u64 %0, t; }" : "=r"(a) : "l"(p));
    return a;
}
__device__ __forceinline__ uint32_t elect_one() {
    uint32_t p;
    asm volatile("{ .reg .pred p; elect.sync _|p, 0xFFFFFFFF; selp.b32 %0, 1, 0, p; }" : "=r"(p));
    return p;
}

#define MBARRIER_INIT(addr, cnt) \
    asm volatile("mbarrier.init.shared.b64 [%0], %1;" :: "r"((uint32_t)(addr)), "r"((uint32_t)(cnt)) : "memory")

#define MBARRIER_WAIT_PARITY(mb, par) do {                                          \
    uint32_t _mb = (uint32_t)(mb), _p = (uint32_t)(par), _d;                        \
    asm volatile("{ .reg .pred p; mbarrier.try_wait.parity.acquire.cta.shared::cta.b64 p, [%1], %2; selp.b32 %0,1,0,p; }" \
        : "=r"(_d) : "r"(_mb), "r"(_p) : "memory");                                 \
    if (!_d) {                                                                      \
        asm volatile("{ .reg .pred P1;\n\t"                                         \
            "WL_%=: mbarrier.try_wait.parity.acquire.cta.shared::cta.b64 P1, [%0], %1, 0x989680;\n\t" \
            "@P1 bra.uni WD_%=;\n\t bra.uni WL_%=;\n\t WD_%=: }"                    \
            :: "r"(_mb), "r"(_p) : "memory");                                       \
    }                                                                               \
} while (0)

#define TCGEN05_ALLOC(sm, n) \
    asm volatile("tcgen05.alloc.cta_group::1.sync.aligned.shared::cta.b32 [%0], %1;" \
        :: "r"((uint32_t)(sm)), "r"((uint32_t)(n)) : "memory")
#define TCGEN05_RELINQ() \
    asm volatile("tcgen05.relinquish_alloc_permit.cta_group::1.sync.aligned;")
#define TCGEN05_DEALLOC(t, n) \
    asm volatile("tcgen05.dealloc.cta_group::1.sync.aligned.b32 %0, %1;" :: "r"(t), "r"((uint32_t)(n)))
#define TCGEN05_COMMIT(mb) \
    asm volatile("tcgen05.commit.cta_group::1.mbarrier::arrive::one.shared::cluster.b64 [%0];" \
        :: "r"((uint32_t)(mb)) : "memory")
#define TCGEN05_WAIT_LD()  asm volatile("tcgen05.wait::ld.sync.aligned;" ::: "memory")
#define TCGEN05_FENCE_AFTER() asm volatile("tcgen05.fence::after_thread_sync;" ::: "memory")

#define TCGEN05_LD_X16(r, addr) \
    asm volatile("tcgen05.ld.sync.aligned.32x32b.x16.b32 " \
        "{%0,%1,%2,%3,%4,%5,%6,%7,%8,%9,%10,%11,%12,%13,%14,%15}, [%16];" \
        : "=r"((r)[0]),"=r"((r)[1]),"=r"((r)[2]),"=r"((r)[3]),   \
          "=r"((r)[4]),"=r"((r)[5]),"=r"((r)[6]),"=r"((r)[7]),   \
          "=r"((r)[8]),"=r"((r)[9]),"=r"((r)[10]),"=r"((r)[11]), \
          "=r"((r)[12]),"=r"((r)[13]),"=r"((r)[14]),"=r"((r)[15]) \
        : "r"(addr))

// SW128 K-major smem descriptor (layout=2, version=1, SBO=64, LBO=1)
__device__ __forceinline__ uint64_t make_desc_sw128(uint32_t addr) {
    return ((uint64_t)2 << 61) | ((uint64_t)1 << 46) | ((uint64_t)64 << 32) |
           ((uint64_t)1 << 16) | ((uint64_t)(addr >> 4) & 0x3FFF);
}

__device__ __forceinline__ void mma_tf32_ss(uint32_t d, uint64_t ad, uint64_t bd,
                                            uint32_t idesc, uint32_t en) {
    asm volatile(
        "{ .reg .pred p; setp.ne.u32 p, %4, 0;\n\t"
        "tcgen05.mma.cta_group::1.kind::tf32 [%0], %1, %2, %3, {%5,%5,%5,%5}, p; }\n"
        :: "r"(d), "l"(ad), "l"(bd), "r"(idesc), "r"(en), "r"(0u) : "memory");
}
#endif // HAS_TCGEN05

// ---------------- main kernel: tile = (batch, image row), M=128 (112 real) ----------------
// 6 stages: (dy in 0..2) x (channel half in 0..1). Per stage: stage 130 pixel-rows x 32ch
// of u (powers computed in regs), then 36 MMAs: dx in 0..2 via A-desc row shift +dx*8.
__global__ __launch_bounds__(NTHREADS, 2) void conv_tc_kernel(
    const float* __restrict__ img,
    const float* __restrict__ wts,
    float* __restrict__ out)
{
#if HAS_TCGEN05
    extern __shared__ char smem[];
    const uint32_t sb = smem_u32(smem);
    const int tid = threadIdx.x, wid = tid >> 5, lane = tid & 31;
    const int bx = blockIdx.x;
    const int b = bx / 112, y = bx - b * 112;

    if (wid == 0) { TCGEN05_ALLOC(sb + OFF_TMEM, 256); TCGEN05_RELINQ(); }
    if (tid == 0) MBARRIER_INIT(sb + OFF_MBAR0, 1);
    __syncthreads();
    uint32_t tmem;
    asm volatile("ld.shared.b32 %0, [%1];" : "=r"(tmem) : "r"(sb + OFF_TMEM));

    // staging quads: q0=2*tid, q1=2*tid+1 (rows 0..127), q2=1024+tid (rows 128/129, tid<16)
    const int q0 = 2 * tid, q1 = 2 * tid + 1, q2 = 1024 + tid;
    const bool hasq2 = (tid < 16);
    // float-offset within (pixrow-base plane region): (q>>3)*64 + (q&7)*4
    const int qo0 = (q0 >> 3) * 64 + (q0 & 7) * 4;
    const int qo1 = (q1 >> 3) * 64 + (q1 & 7) * 4;
    const int qo2 = (q2 >> 3) * 64 + (q2 & 7) * 4;
    // swizzled smem byte offsets: off = q*16; sw = off ^ ((off>>3)&0x70)
    const uint32_t sw0 = (uint32_t)(q0 * 16) ^ (((uint32_t)(q0 * 2)) & 0x70);
    const uint32_t sw1 = (uint32_t)(q1 * 16) ^ (((uint32_t)(q1 * 2)) & 0x70);
    const uint32_t sw2 = (uint32_t)(q2 * 16) ^ (((uint32_t)(q2 * 2)) & 0x70);
    // B staging: thread -> (o = tid>>3, kq = tid&7), same quad formula
    const uint32_t bsw = (uint32_t)(tid * 16) ^ (((uint32_t)(tid * 2)) & 0x70);
    const int bo = tid >> 3, bq = tid & 7;

    const float* u1p = g_u1 + (size_t)b * PS2 * 64;

    float4 u4a, u4b, u4c, bw0, bw1, bw2;

    #define PREFETCH(S) do {                                                     \
        int _dy = (S) >> 1, _c0 = (((S) & 1) << 5);                              \
        const float* _pb = u1p + (size_t)(y + _dy) * (PAD_W * 64) + _c0;         \
        u4a = *(const float4*)(_pb + qo0);                                       \
        u4b = *(const float4*)(_pb + qo1);                                       \
        if (hasq2) u4c = *(const float4*)(_pb + qo2);                            \
        const float* _wb = g_wtfR + (((S) * 3) * C_OUT + bo) * 32 + bq * 4;      \
        bw0 = *(const float4*)(_wb);                                             \
        bw1 = *(const float4*)(_wb + C_OUT * 32);                                \
        bw2 = *(const float4*)(_wb + 2 * C_OUT * 32);                            \
    } while (0)

    #define STORE_A(U, SW) do {                                                  \
        float4 _r2, _r3;                                                         \
        const float* _p = &(U).x; float* _q2 = &_r2.x; float* _q3 = &_r3.x;      \
        _Pragma("unroll")                                                        \
        for (int _j = 0; _j < 4; ++_j) {                                         \
            float _v = _p[_j], _v2 = _v * _v;                                    \
            _q2[_j] = tf32r_(_v2); _q3[_j] = tf32r_(_v2 * _v);                   \
        }                                                                        \
        *(float4*)(smem + OFF_A + 0 * A_PSTRIDE + (SW)) = (U);                   \
        *(float4*)(smem + OFF_A + 1 * A_PSTRIDE + (SW)) = _r2;                   \
        *(float4*)(smem + OFF_A + 2 * A_PSTRIDE + (SW)) = _r3;                   \
    } while (0)

    PREFETCH(0);

    int ph = 0;
    for (int s = 0; s < NSTAGE; ++s) {
        if (s > 0) { MBARRIER_WAIT_PARITY(sb + OFF_MBAR0, ph); ph ^= 1; }

        STORE_A(u4a, sw0);
        STORE_A(u4b, sw1);
        if (hasq2) STORE_A(u4c, sw2);
        *(float4*)(smem + OFF_B + 0 * B_DSTRIDE + bsw) = bw0;
        *(float4*)(smem + OFF_B + 1 * B_DSTRIDE + bsw) = bw1;
        *(float4*)(smem + OFF_B + 2 * B_DSTRIDE + bsw) = bw2;
        asm volatile("fence.proxy.async.shared::cta;" ::: "memory");
        __syncthreads();

        if (wid == 0 && elect_one()) {
            const uint64_t ad1 = make_desc_sw128(sb + OFF_A);
            const uint64_t ad2 = make_desc_sw128(sb + OFF_A + A_PSTRIDE);
            const uint64_t ad3 = make_desc_sw128(sb + OFF_A + 2 * A_PSTRIDE);
            #pragma unroll
            for (int st = 0; st < 4; ++st) {
                #pragma unroll
                for (int dx = 0; dx < 3; ++dx) {
                    const uint64_t bd = make_desc_sw128(sb + OFF_B + dx * B_DSTRIDE) + st * 2;
                    const uint32_t aoff = dx * 8 + st * 2;   // row shift + k-step, 16B units
                    uint32_t en = (s > 0 || st > 0 || dx > 0) ? 1u : 0u;
                    mma_tf32_ss(tmem + 0,   ad1 + aoff, bd, IDESC_TF32, en);
                    mma_tf32_ss(tmem + 64,  ad2 + aoff, bd, IDESC_TF32, en);
                    mma_tf32_ss(tmem + 128, ad3 + aoff, bd, IDESC_TF32, en);
                }
            }
            TCGEN05_COMMIT(sb + OFF_MBAR0);
        }

        if (s + 1 < NSTAGE) PREFETCH(s + 1);
    }
    MBARRIER_WAIT_PARITY(sb + OFF_MBAR0, ph);

    // ---- fused epilogue from TMEM (16 warps: warp -> (m-subpartition, 16-col group)) ----
    TCGEN05_FENCE_AFTER();
    const int msub = wid & 3;
    const int n0   = (wid >> 2) * 16;
    const int mloc = msub * 32 + lane;          // 0..127; valid if < 112

    {
        uint32_t a1[16], a2[16], a3[16];
        TCGEN05_LD_X16(a1, tmem + 0   + n0);
        TCGEN05_LD_X16(a2, tmem + 64  + n0);
        TCGEN05_LD_X16(a3, tmem + 128 + n0);
        TCGEN05_WAIT_LD();
        if (mloc < 112) {
            #pragma unroll
            for (int ni = 0; ni < 16; ++ni) {
                const int o = n0 + ni;
                float res = epilogue(__ldg(g_wsum + o),
                                     __uint_as_float(a1[ni]),
                                     __uint_as_float(a2[ni]),
                                     __uint_as_float(a3[ni]));
                out[(size_t)(b * C_OUT + o) * L_TOT + y * 112 + mloc] = res;
            }
        }
    }

    __syncthreads();
    if (wid == 0) TCGEN05_DEALLOC(tmem, 256);
#else
    // ---------- fallback for non-sm_103a compilation passes (never runs on GB300) ----------
    const int tid = threadIdx.x;
    const int bx = blockIdx.x;
    const int b = bx / 112, y = bx - b * 112;
    const float* imgb = img + (size_t)b * C_IN * L_TOT;

    for (int idx = tid; idx < 112 * C_OUT; idx += NTHREADS) {
        int x = idx % 112, o = idx / 112;
        float c1 = 0.f, c2 = 0.f, c3 = 0.f;
        for (int k = 0; k < K_TOT; ++k) {
            int c = k / 9, r = k - c * 9, dy = r / 3, dx = r - dy * 3;
            int iy = y + dy - 1, ix = x + dx - 1;
            float v = 0.f;
            if ((unsigned)iy < 112u && (unsigned)ix < 112u)
                v = imgb[c * L_TOT + iy * 112 + ix];
            float w = wts[o * K_TOT + k];
            c1 += v * w; c2 += v * v * w; c3 += v * v * v * w;
        }
        out[(size_t)(b * C_OUT + o) * L_TOT + y * 112 + x] = epilogue(g_wsum[o], c1, c2, c3);
    }
#endif
}

extern "C" void kernel_launch(void* const* d_in, const int* in_sizes, int n_in,
                              void* d_out, int out_size) {
    const float* img = (const float*)d_in[0];
    const float* wts = (const float*)d_in[1];
    float* out = (float*)d_out;

    int B = in_sizes[0] / (C_IN * L_TOT);   // 8

    cudaFuncSetAttribute(conv_tc_kernel, cudaFuncAttributeMaxDynamicSharedMemorySize, SMEM_TOTAL);

    wprep_kernel<<<4, 512>>>(wts);
    {
        dim3 pg((PAD_S + 31) / 32, B);
        uprep_kernel<<<pg, dim3(32, 8)>>>(img);
    }
    conv_tc_kernel<<<B * 112, NTHREADS, SMEM_TOTAL>>>(img, wts, out);
}